// round 1
// baseline (speedup 1.0000x reference)
#include <cuda_runtime.h>

#define DIMC 192
#define BB   4
#define HH   256
#define WW   256
#define RR   48
#define KK9  9
#define EPSV 1e-5f

// Scratch (allocation-free rule: __device__ globals)
__device__ float g_pooled[BB * DIMC];       // [b*DIM + c]
__device__ float g_wt[BB * DIMC * KK9];     // [b*DIM*9 + c*9 + k]

// ---------------------------------------------------------------------------
// Kernel 1: global average pool per (b, c) plane. 768 blocks x 256 threads.
// ---------------------------------------------------------------------------
__global__ __launch_bounds__(256) void pool_kernel(const float* __restrict__ x) {
    const int plane = blockIdx.x;  // b*DIM + c
    const float4* __restrict__ p =
        reinterpret_cast<const float4*>(x + (size_t)plane * HH * WW);
    const int tid = threadIdx.x;

    float s = 0.f;
    // 16384 float4 per plane / 256 threads = 64 per thread
    #pragma unroll 8
    for (int i = tid; i < (HH * WW) / 4; i += 256) {
        float4 v = p[i];
        s += (v.x + v.y) + (v.z + v.w);
    }

    __shared__ float sh[8];
    #pragma unroll
    for (int o = 16; o > 0; o >>= 1) s += __shfl_down_sync(0xffffffffu, s, o);
    if ((tid & 31) == 0) sh[tid >> 5] = s;
    __syncthreads();
    if (tid < 8) {
        float v = sh[tid];
        #pragma unroll
        for (int o = 4; o > 0; o >>= 1) v += __shfl_down_sync(0xffu, v, o);
        if (tid == 0) g_pooled[plane] = v * (1.0f / (HH * WW));
    }
}

// ---------------------------------------------------------------------------
// Kernel 2: dynamic weight MLP + BN(eval) + ReLU + mask. One block, 256 thr.
//   t[b][j]  = relu(BN(pooled[b] . w1[j]))            (192 dots of len 192)
//   wt[b][o] = t[b] . w2[o] + b2[o], masked by 'A'    (6912 dots of len 48)
// ---------------------------------------------------------------------------
__global__ __launch_bounds__(256) void weights_kernel(
    const float* __restrict__ w1,
    const float* __restrict__ gamma,
    const float* __restrict__ beta,
    const float* __restrict__ rmean,
    const float* __restrict__ rvar,
    const float* __restrict__ w2,
    const float* __restrict__ b2) {
    __shared__ float tsh[BB * RR];  // 192
    const int tid = threadIdx.x;

    if (tid < BB * RR) {
        const int b = tid / RR, j = tid % RR;
        const float* __restrict__ pb = &g_pooled[b * DIMC];
        const float* __restrict__ wj = &w1[j * DIMC];
        float acc = 0.f;
        #pragma unroll 4
        for (int c = 0; c < DIMC; c++) acc = fmaf(pb[c], wj[c], acc);
        acc = gamma[j] * (acc - rmean[j]) * rsqrtf(rvar[j] + EPSV) + beta[j];
        tsh[tid] = fmaxf(acc, 0.f);
    }
    __syncthreads();

    const int TOT = BB * DIMC * KK9;  // 6912
    for (int i = tid; i < TOT; i += 256) {
        const int b = i / (DIMC * KK9);
        const int o = i % (DIMC * KK9);
        const int kidx = o % KK9;
        const int krow = kidx / 3, kcol = kidx % 3;
        // mask 'A': zero (1,1),(1,2) and all of row 2
        const bool masked = (krow == 2) || (krow == 1 && kcol >= 1);
        float val = 0.f;
        if (!masked) {
            float acc = b2[o];
            const float* __restrict__ ts = &tsh[b * RR];
            const float* __restrict__ wr = &w2[(size_t)o * RR];
            #pragma unroll
            for (int j = 0; j < RR; j++) acc = fmaf(ts[j], wr[j], acc);
            val = acc;
        }
        g_wt[i] = val;
    }
}

// ---------------------------------------------------------------------------
// Kernel 3: 4-tap causal depthwise conv (taps (0,0),(0,1),(0,2),(1,0)),
// zero padding. One block per (b,c) plane; float4 output quads.
//   out[y][x] = w00*in[y-1][x-1] + w01*in[y-1][x] + w02*in[y-1][x+1]
//             + w10*in[y][x-1]   + bias[c]
// ---------------------------------------------------------------------------
__global__ __launch_bounds__(256) void conv_kernel(
    const float* __restrict__ x,
    const float* __restrict__ bias,
    float* __restrict__ out) {
    const int plane = blockIdx.x;         // b*DIM + c
    const int c = plane % DIMC;
    const float* __restrict__ wv = &g_wt[plane * KK9];
    const float w00 = wv[0], w01 = wv[1], w02 = wv[2], w10 = wv[3];
    const float bvv = bias[c];

    const float* __restrict__ in = x + (size_t)plane * HH * WW;
    float* __restrict__ op = out + (size_t)plane * HH * WW;

    const int tid = threadIdx.x;
    const int qx = tid & 63;   // quad 0..63 (cols 4qx..4qx+3)
    const int ry = tid >> 6;   // row phase 0..3
    const int col0 = qx * 4;

    for (int y = ry; y < HH; y += 4) {
        const float* __restrict__ rowC = in + y * WW;
        const float* __restrict__ rowU = rowC - WW;

        float4 u = make_float4(0.f, 0.f, 0.f, 0.f);
        float um1 = 0.f, up4 = 0.f;
        if (y > 0) {
            u = *reinterpret_cast<const float4*>(rowU + col0);
            um1 = (qx > 0) ? rowU[col0 - 1] : 0.f;
            up4 = (qx < 63) ? rowU[col0 + 4] : 0.f;
        }
        const float4 cv = *reinterpret_cast<const float4*>(rowC + col0);
        const float cm1 = (qx > 0) ? rowC[col0 - 1] : 0.f;

        float4 o;
        o.x = fmaf(w00, um1, fmaf(w01, u.x, fmaf(w02, u.y, fmaf(w10, cm1,  bvv))));
        o.y = fmaf(w00, u.x, fmaf(w01, u.y, fmaf(w02, u.z, fmaf(w10, cv.x, bvv))));
        o.z = fmaf(w00, u.y, fmaf(w01, u.z, fmaf(w02, u.w, fmaf(w10, cv.y, bvv))));
        o.w = fmaf(w00, u.z, fmaf(w01, u.w, fmaf(w02, up4, fmaf(w10, cv.z, bvv))));
        *reinterpret_cast<float4*>(op + y * WW + col0) = o;
    }
}

// ---------------------------------------------------------------------------
// Launch. Inputs (metadata order):
//  0:x 1:w1 2:gamma 3:beta 4:running_mean 5:running_var 6:w2 7:b2 8:bias
// ---------------------------------------------------------------------------
extern "C" void kernel_launch(void* const* d_in, const int* in_sizes, int n_in,
                              void* d_out, int out_size) {
    const float* x     = (const float*)d_in[0];
    const float* w1    = (const float*)d_in[1];
    const float* gamma = (const float*)d_in[2];
    const float* beta  = (const float*)d_in[3];
    const float* rmean = (const float*)d_in[4];
    const float* rvar  = (const float*)d_in[5];
    const float* w2    = (const float*)d_in[6];
    const float* b2    = (const float*)d_in[7];
    const float* bias  = (const float*)d_in[8];
    float* out = (float*)d_out;

    pool_kernel<<<BB * DIMC, 256>>>(x);
    weights_kernel<<<1, 256>>>(w1, gamma, beta, rmean, rvar, w2, b2);
    conv_kernel<<<BB * DIMC, 256>>>(x, bias, out);
}

// round 2
// speedup vs baseline: 1.3760x; 1.3760x over previous
#include <cuda_runtime.h>

#define DIMC 192
#define BB   4
#define HH   256
#define WW   256
#define RR   48
#define KK9  9
#define EPSV 1e-5f

// Scratch (allocation-free rule: __device__ globals)
__device__ float g_pooled[BB * DIMC];       // [b*DIM + c]
__device__ float g_wt[BB * DIMC * KK9];     // [b*DIM*9 + c*9 + k]

// ---------------------------------------------------------------------------
// Kernel 1: global average pool per (b, c) plane. 768 blocks x 256 threads.
// (measured 79% DRAM — at the LTS ceiling, keep as-is)
// ---------------------------------------------------------------------------
__global__ __launch_bounds__(256) void pool_kernel(const float* __restrict__ x) {
    const int plane = blockIdx.x;  // b*DIM + c
    const float4* __restrict__ p =
        reinterpret_cast<const float4*>(x + (size_t)plane * HH * WW);
    const int tid = threadIdx.x;

    float s = 0.f;
    #pragma unroll 8
    for (int i = tid; i < (HH * WW) / 4; i += 256) {
        float4 v = p[i];
        s += (v.x + v.y) + (v.z + v.w);
    }

    __shared__ float sh[8];
    #pragma unroll
    for (int o = 16; o > 0; o >>= 1) s += __shfl_down_sync(0xffffffffu, s, o);
    if ((tid & 31) == 0) sh[tid >> 5] = s;
    __syncthreads();
    if (tid < 8) {
        float v = sh[tid];
        #pragma unroll
        for (int o = 4; o > 0; o >>= 1) v += __shfl_down_sync(0xffu, v, o);
        if (tid == 0) g_pooled[plane] = v * (1.0f / (HH * WW));
    }
}

// ---------------------------------------------------------------------------
// Kernel 2: dynamic weight MLP + BN(eval) + ReLU + mask. 27 blocks x 256 thr.
// Each block redundantly computes the tiny hidden vector t (192 dots of 192),
// then produces its own 256 of the 6912 outputs (w2 rows streamed in parallel
// across blocks instead of by one SM).
// ---------------------------------------------------------------------------
__global__ __launch_bounds__(256) void weights_kernel(
    const float* __restrict__ w1,
    const float* __restrict__ gamma,
    const float* __restrict__ beta,
    const float* __restrict__ rmean,
    const float* __restrict__ rvar,
    const float* __restrict__ w2,
    const float* __restrict__ b2) {
    __shared__ float tsh[BB * RR];  // 192
    const int tid = threadIdx.x;

    if (tid < BB * RR) {
        const int b = tid / RR, j = tid % RR;
        const float* __restrict__ pb = &g_pooled[b * DIMC];
        const float* __restrict__ wj = &w1[j * DIMC];
        float acc = 0.f;
        #pragma unroll 8
        for (int c = 0; c < DIMC; c++) acc = fmaf(pb[c], wj[c], acc);
        acc = gamma[j] * (acc - rmean[j]) * rsqrtf(rvar[j] + EPSV) + beta[j];
        tsh[tid] = fmaxf(acc, 0.f);
    }
    __syncthreads();

    const int i = blockIdx.x * 256 + tid;      // 0..6911
    const int b = i / (DIMC * KK9);
    const int o = i % (DIMC * KK9);
    const int kidx = o % KK9;
    const int krow = kidx / 3, kcol = kidx % 3;
    // mask 'A': zero (1,1),(1,2) and all of row 2
    const bool masked = (krow == 2) || (krow == 1 && kcol >= 1);
    float val = 0.f;
    if (!masked) {
        float acc = b2[o];
        const float* __restrict__ ts = &tsh[b * RR];
        const float* __restrict__ wr = &w2[(size_t)o * RR];
        #pragma unroll
        for (int j = 0; j < RR; j++) acc = fmaf(ts[j], wr[j], acc);
        val = acc;
    }
    g_wt[i] = val;
}

// ---------------------------------------------------------------------------
// Kernel 3: 4-tap causal depthwise conv, taps (0,0),(0,1),(0,2),(1,0), zero pad.
//   out[y][x] = w00*in[y-1][x-1] + w01*in[y-1][x] + w02*in[y-1][x+1]
//             + w10*in[y][x-1]   + bias[c]
// One block per plane. Thread = (quad column qx 0..63, row chunk 0..3 of 64
// consecutive rows). Previous row carried in registers: per row iteration just
// 1x LDG.128 + 2 shfls (+ predicated warp-boundary scalar), 16 FMA, 1 STG.128.
// ---------------------------------------------------------------------------
__global__ __launch_bounds__(256) void conv_kernel(
    const float* __restrict__ x,
    const float* __restrict__ bias,
    float* __restrict__ out) {
    const int plane = blockIdx.x;         // b*DIM + c
    const int c = plane % DIMC;
    const float* __restrict__ wv = &g_wt[plane * KK9];
    const float w00 = wv[0], w01 = wv[1], w02 = wv[2], w10 = wv[3];
    const float bvv = bias[c];

    const float* __restrict__ in = x + (size_t)plane * HH * WW;
    float* __restrict__ op = out + (size_t)plane * HH * WW;

    const int tid   = threadIdx.x;
    const int qx    = tid & 63;     // quad column: cols 4qx..4qx+3
    const int chunk = tid >> 6;     // 0..3, rows [chunk*64, chunk*64+64)
    const int lane  = tid & 31;
    const int col0  = qx * 4;
    const int y0    = chunk * 64;

    // previous-row state
    float4 p;
    float pm1, pp4;
    if (chunk == 0) {
        p = make_float4(0.f, 0.f, 0.f, 0.f);
        pm1 = 0.f; pp4 = 0.f;
    } else {
        const float* __restrict__ rU = in + (y0 - 1) * WW;
        p   = *reinterpret_cast<const float4*>(rU + col0);
        pm1 = (qx > 0)  ? rU[col0 - 1] : 0.f;
        pp4 = (qx < 63) ? rU[col0 + 4] : 0.f;
    }

    #pragma unroll 4
    for (int y = y0; y < y0 + 64; y++) {
        const float* __restrict__ rC = in + y * WW;
        const float4 cv = *reinterpret_cast<const float4*>(rC + col0);

        // cm1 = rC[col0-1] = lane (qx-1)'s cv.w
        float cm1 = __shfl_up_sync(0xffffffffu, cv.w, 1);
        if (lane == 0) cm1 = (qx > 0) ? rC[col0 - 1] : 0.f;

        float4 o;
        o.x = fmaf(w00, pm1, fmaf(w01, p.x, fmaf(w02, p.y, fmaf(w10, cm1,  bvv))));
        o.y = fmaf(w00, p.x, fmaf(w01, p.y, fmaf(w02, p.z, fmaf(w10, cv.x, bvv))));
        o.z = fmaf(w00, p.y, fmaf(w01, p.z, fmaf(w02, p.w, fmaf(w10, cv.y, bvv))));
        o.w = fmaf(w00, p.z, fmaf(w01, p.w, fmaf(w02, pp4, fmaf(w10, cv.z, bvv))));
        *reinterpret_cast<float4*>(op + y * WW + col0) = o;

        // carry current row to next iteration
        // pp4_next = rC[col0+4] = lane (qx+1)'s cv.x
        float nx = __shfl_down_sync(0xffffffffu, cv.x, 1);
        if (lane == 31) nx = (qx < 63) ? rC[col0 + 4] : 0.f;
        pm1 = cm1;
        pp4 = nx;
        p   = cv;
    }
}

// ---------------------------------------------------------------------------
// Launch. Inputs (metadata order):
//  0:x 1:w1 2:gamma 3:beta 4:running_mean 5:running_var 6:w2 7:b2 8:bias
// ---------------------------------------------------------------------------
extern "C" void kernel_launch(void* const* d_in, const int* in_sizes, int n_in,
                              void* d_out, int out_size) {
    const float* x     = (const float*)d_in[0];
    const float* w1    = (const float*)d_in[1];
    const float* gamma = (const float*)d_in[2];
    const float* beta  = (const float*)d_in[3];
    const float* rmean = (const float*)d_in[4];
    const float* rvar  = (const float*)d_in[5];
    const float* w2    = (const float*)d_in[6];
    const float* b2    = (const float*)d_in[7];
    const float* bias  = (const float*)d_in[8];
    float* out = (float*)d_out;

    pool_kernel<<<BB * DIMC, 256>>>(x);
    weights_kernel<<<(BB * DIMC * KK9) / 256, 256>>>(w1, gamma, beta, rmean, rvar, w2, b2);
    conv_kernel<<<BB * DIMC, 256>>>(x, bias, out);
}